// round 1
// baseline (speedup 1.0000x reference)
#include <cuda_runtime.h>
#include <math.h>

#define B_ 8
#define N_ 256
#define D_ 128

// Scratch (device globals — no allocation allowed in kernel_launch)
__device__ float g_h[B_*N_*D_];     // h = nf@Wn + bn            [b][i][d]
__device__ float g_base[B_*N_*D_];  // a_i + be1                 [b][i][d]
__device__ float g_ajT[B_*D_*N_];   // a_j transposed            [b][d][j]

// ---------------------------------------------------------------------------
// Kernel 1: three fused GEMVs per node row:
//   h    = nf @ Wn            + bn
//   base = nf @ We1[0:128]    + be1   (a_i part, bias folded)
//   ajT  = nf @ We1[128:256]          (a_j part, stored d-major for kernel 2)
// Block = 16 rows (one batch), 256 threads: thread (d = t%128, rg = t/128)
// accumulates 8 rows x 3 outputs.
// ---------------------------------------------------------------------------
__global__ void __launch_bounds__(256) precompute_kernel(
    const float* __restrict__ nf,
    const float* __restrict__ Wn,  const float* __restrict__ bn,
    const float* __restrict__ We1, const float* __restrict__ be1)
{
    __shared__ float s_nf[16*128];
    __shared__ float s_t[128*17];   // padded transpose staging for ajT
    const int t  = threadIdx.x;
    const int b  = blockIdx.x >> 4;
    const int i0 = (blockIdx.x & 15) << 4;

    const float* nfrow = nf + (b*N_ + i0)*D_;
    for (int idx = t; idx < 16*128; idx += 256)
        s_nf[idx] = nfrow[idx];
    __syncthreads();

    const int d  = t & 127;
    const int rg = t >> 7;

    float ah[8], aa[8], aj[8];
    #pragma unroll
    for (int r = 0; r < 8; r++) { ah[r] = 0.f; aa[r] = 0.f; aj[r] = 0.f; }

    #pragma unroll 2
    for (int k = 0; k < 128; k++) {
        float wn = Wn [ k       *128 + d];
        float wa = We1[ k       *128 + d];
        float wb = We1[(128 + k)*128 + d];
        #pragma unroll
        for (int r = 0; r < 8; r++) {
            float x = s_nf[(rg*8 + r)*128 + k];   // warp-uniform broadcast
            ah[r] = fmaf(x, wn, ah[r]);
            aa[r] = fmaf(x, wa, aa[r]);
            aj[r] = fmaf(x, wb, aj[r]);
        }
    }

    const float bnd = bn[d], bed = be1[d];
    #pragma unroll
    for (int r = 0; r < 8; r++) {
        int row = rg*8 + r;
        int gi  = (b*N_ + i0 + row)*D_ + d;
        g_h[gi]    = ah[r] + bnd;
        g_base[gi] = aa[r] + bed;
        s_t[d*17 + row] = aj[r];                 // conflict-free (stride 17)
    }
    __syncthreads();

    // write a_j transposed: [b][d][i0..i0+15]
    for (int idx = t; idx < 128*16; idx += 256) {
        int dd = idx >> 4, rr = idx & 15;
        g_ajT[(b*D_ + dd)*N_ + i0 + rr] = s_t[dd*17 + rr];
    }
}

// ---------------------------------------------------------------------------
// Kernel 2: fused edge-MLP scores -> masked softmax -> messages (w@h) ->
//           output GEMM + relu + residual -> layernorm.
// Block = (b, 16-row i-tile), 256 threads. Grid = 128 blocks.
// ---------------------------------------------------------------------------
__global__ void __launch_bounds__(256) fused_kernel(
    const float* __restrict__ nf,
    const int*   __restrict__ adj,
    const float* __restrict__ rel,
    const float* __restrict__ We1,
    const float* __restrict__ We2,
    const float* __restrict__ Wa,
    const float* __restrict__ ba,
    const float* __restrict__ gamma,
    const float* __restrict__ beta,
    float* __restrict__ out)
{
    __shared__ float  s_sc[16*256];   // scores, then softmax weights w
    __shared__ float  s_bt[2048];     // baseT [d*16+i]; reused as x [i*128+d]
    __shared__ float  s_msg[16*128];  // messages
    __shared__ float4 s_w4[128];      // (w_relx, w_rely, w_dist, We2)[d]

    const int t  = threadIdx.x;
    const int b  = blockIdx.x >> 4;
    const int i0 = (blockIdx.x & 15) << 4;

    // ---- phase 0: stage base (transposed) and rel-weight columns ----
    for (int idx = t; idx < 2048; idx += 256) {
        int i = idx >> 7, d = idx & 127;
        s_bt[d*16 + i] = g_base[(b*N_ + i0 + i)*D_ + d];
    }
    if (t < 128)
        s_w4[t] = make_float4(We1[256*128 + t], We1[257*128 + t],
                              We1[258*128 + t], We2[t]);
    __syncthreads();

    // ---- phase 1: edge scores. lane <-> j (j = t), loop d outer, i inner.
    {
        const int j = t;
        float rx[16], ry[16], rd[16];
        unsigned mbits = 0u;
        #pragma unroll
        for (int i = 0; i < 16; i++) {
            float2 r = *(const float2*)(rel + (size_t)(((b*N_) + (i0 + i))*N_ + j)*2);
            rx[i] = r.x; ry[i] = r.y;
            rd[i] = sqrtf(r.x*r.x + r.y*r.y);
            if (adj[((b*N_) + (i0 + i))*N_ + j] != 0) mbits |= (1u << i);
        }
        float s[16];
        #pragma unroll
        for (int i = 0; i < 16; i++) s[i] = 0.f;

        const float* ajp = g_ajT + (size_t)b*D_*N_ + j;
        #pragma unroll 2
        for (int d = 0; d < 128; d++) {
            float  ajv = ajp[d*N_];            // coalesced 128B per warp
            float4 w4  = s_w4[d];              // broadcast
            const float4* bp = (const float4*)(s_bt + d*16);
            #pragma unroll
            for (int ig = 0; ig < 4; ig++) {
                float4 bs = bp[ig];            // broadcast LDS.128
                float v0 = fmaf(rx[ig*4+0], w4.x, fmaf(ry[ig*4+0], w4.y, fmaf(rd[ig*4+0], w4.z, bs.x + ajv)));
                float v1 = fmaf(rx[ig*4+1], w4.x, fmaf(ry[ig*4+1], w4.y, fmaf(rd[ig*4+1], w4.z, bs.y + ajv)));
                float v2 = fmaf(rx[ig*4+2], w4.x, fmaf(ry[ig*4+2], w4.y, fmaf(rd[ig*4+2], w4.z, bs.z + ajv)));
                float v3 = fmaf(rx[ig*4+3], w4.x, fmaf(ry[ig*4+3], w4.y, fmaf(rd[ig*4+3], w4.z, bs.w + ajv)));
                s[ig*4+0] = fmaf(fmaxf(v0, 0.f), w4.w, s[ig*4+0]);
                s[ig*4+1] = fmaf(fmaxf(v1, 0.f), w4.w, s[ig*4+1]);
                s[ig*4+2] = fmaf(fmaxf(v2, 0.f), w4.w, s[ig*4+2]);
                s[ig*4+3] = fmaf(fmaxf(v3, 0.f), w4.w, s[ig*4+3]);
            }
        }
        #pragma unroll
        for (int i = 0; i < 16; i++)
            s_sc[i*256 + j] = ((mbits >> i) & 1u) ? s[i] : -1e30f;
        // note: be2 omitted — softmax is shift-invariant.
    }
    __syncthreads();

    // ---- phase 2: masked softmax over j (warp w handles rows w and w+8)
    {
        const int w = t >> 5, lane = t & 31;
        #pragma unroll
        for (int ii = 0; ii < 2; ii++) {
            int i = w + ii*8;
            float v[8]; float m = -3.0e38f;
            #pragma unroll
            for (int k = 0; k < 8; k++) { v[k] = s_sc[i*256 + lane + 32*k]; m = fmaxf(m, v[k]); }
            #pragma unroll
            for (int o = 16; o > 0; o >>= 1) m = fmaxf(m, __shfl_xor_sync(0xffffffffu, m, o));
            float sum = 0.f;
            #pragma unroll
            for (int k = 0; k < 8; k++) { v[k] = __expf(v[k] - m); sum += v[k]; }
            #pragma unroll
            for (int o = 16; o > 0; o >>= 1) sum += __shfl_xor_sync(0xffffffffu, sum, o);
            float inv = 1.0f / sum;
            #pragma unroll
            for (int k = 0; k < 8; k++) s_sc[i*256 + lane + 32*k] = v[k] * inv;
        }
    }
    __syncthreads();

    // ---- phase 3: messages[i][d] = sum_j w[i][j] * h[j][d]
    {
        const int d = t & 127, g = t >> 7;
        float m[8];
        #pragma unroll
        for (int r = 0; r < 8; r++) m[r] = 0.f;
        const float* hp = g_h + (size_t)b*N_*D_ + d;
        #pragma unroll 2
        for (int j = 0; j < 256; j += 4) {
            float hv0 = hp[(j+0)*D_];
            float hv1 = hp[(j+1)*D_];
            float hv2 = hp[(j+2)*D_];
            float hv3 = hp[(j+3)*D_];
            #pragma unroll
            for (int r = 0; r < 8; r++) {
                const float4 wq = *(const float4*)(s_sc + (g*8 + r)*256 + j);
                m[r] = fmaf(wq.w, hv3, fmaf(wq.z, hv2, fmaf(wq.y, hv1, fmaf(wq.x, hv0, m[r]))));
            }
        }
        #pragma unroll
        for (int r = 0; r < 8; r++) s_msg[(g*8 + r)*128 + d] = m[r];
    }
    __syncthreads();

    // ---- phase 4: aggregated = relu(msg @ Wa + ba); x = nf + aggregated
    {
        const int dq = t & 127, g = t >> 7;
        float a[8];
        #pragma unroll
        for (int r = 0; r < 8; r++) a[r] = 0.f;
        #pragma unroll 4
        for (int d = 0; d < 128; d++) {
            float wv = Wa[d*128 + dq];
            #pragma unroll
            for (int r = 0; r < 8; r++)
                a[r] = fmaf(s_msg[(g*8 + r)*128 + d], wv, a[r]);
        }
        const float bav = ba[dq];
        #pragma unroll
        for (int r = 0; r < 8; r++) {
            int i = g*8 + r;
            float x = nf[(b*N_ + i0 + i)*D_ + dq] + fmaxf(a[r] + bav, 0.f);
            s_bt[i*128 + dq] = x;    // baseT dead after phase 1; reuse as x
        }
    }
    __syncthreads();

    // ---- phase 5: layernorm over d, write output
    {
        const int w = t >> 5, lane = t & 31;
        #pragma unroll
        for (int ii = 0; ii < 2; ii++) {
            int i = w + ii*8;
            float4 xv = *(const float4*)(s_bt + i*128 + lane*4);
            float sm = xv.x + xv.y + xv.z + xv.w;
            float sq = fmaf(xv.x, xv.x, fmaf(xv.y, xv.y, fmaf(xv.z, xv.z, xv.w*xv.w)));
            #pragma unroll
            for (int o = 16; o > 0; o >>= 1) {
                sm += __shfl_xor_sync(0xffffffffu, sm, o);
                sq += __shfl_xor_sync(0xffffffffu, sq, o);
            }
            float mu   = sm * (1.0f/128.0f);
            float var  = fmaf(sq, 1.0f/128.0f, -mu*mu);
            float rstd = rsqrtf(var + 1e-5f);
            float4 gv = *(const float4*)(gamma + lane*4);
            float4 bv = *(const float4*)(beta  + lane*4);
            float4 o4;
            o4.x = fmaf((xv.x - mu)*rstd, gv.x, bv.x);
            o4.y = fmaf((xv.y - mu)*rstd, gv.y, bv.y);
            o4.z = fmaf((xv.z - mu)*rstd, gv.z, bv.z);
            o4.w = fmaf((xv.w - mu)*rstd, gv.w, bv.w);
            *(float4*)(out + (size_t)(b*N_ + i0 + i)*D_ + lane*4) = o4;
        }
    }
}

extern "C" void kernel_launch(void* const* d_in, const int* in_sizes, int n_in,
                              void* d_out, int out_size)
{
    const float* nf    = (const float*)d_in[0];
    const int*   adj   = (const int*)  d_in[1];
    const float* rel   = (const float*)d_in[2];
    const float* Wn    = (const float*)d_in[3];
    const float* bn    = (const float*)d_in[4];
    const float* We1   = (const float*)d_in[5];
    const float* be1   = (const float*)d_in[6];
    const float* We2   = (const float*)d_in[7];
    // d_in[8] = be2: unused (softmax shift-invariance makes it a no-op)
    const float* Wa    = (const float*)d_in[9];
    const float* ba    = (const float*)d_in[10];
    const float* gamma = (const float*)d_in[11];
    const float* beta  = (const float*)d_in[12];
    float* out = (float*)d_out;

    precompute_kernel<<<128, 256>>>(nf, Wn, bn, We1, be1);
    fused_kernel<<<128, 256>>>(nf, adj, rel, We1, We2, Wa, ba, gamma, beta, out);
}

// round 2
// speedup vs baseline: 1.2243x; 1.2243x over previous
#include <cuda_runtime.h>
#include <math.h>

#define B_ 8
#define N_ 256
#define D_ 128

// Scratch (device globals — no allocation allowed in kernel_launch)
__device__ float g_h[B_*N_*D_];     // h = nf@Wn + bn            [b][i][d]
__device__ float g_base[B_*N_*D_];  // a_i + be1                 [b][i][d]
__device__ float g_ajT[B_*D_*N_];   // a_j transposed            [b][d][j]

// ---------------------------------------------------------------------------
// Kernel 1: three fused GEMVs per node row (8-row tiles, 256 blocks):
//   h    = nf @ Wn            + bn
//   base = nf @ We1[0:128]    + be1   (a_i part, bias folded)
//   ajT  = nf @ We1[128:256]          (a_j part, stored d-major for kernel 2)
// ---------------------------------------------------------------------------
__global__ void __launch_bounds__(256, 3) precompute_kernel(
    const float* __restrict__ nf,
    const float* __restrict__ Wn,  const float* __restrict__ bn,
    const float* __restrict__ We1, const float* __restrict__ be1)
{
    __shared__ float s_nf[8*128];
    __shared__ float s_t[128*9];    // padded transpose staging for ajT
    const int t  = threadIdx.x;
    const int b  = blockIdx.x >> 5;
    const int i0 = (blockIdx.x & 31) << 3;

    const float* nfrow = nf + (b*N_ + i0)*D_;
    for (int idx = t; idx < 8*128; idx += 256)
        s_nf[idx] = nfrow[idx];
    __syncthreads();

    const int d  = t & 127;
    const int rg = t >> 7;          // 0/1 -> rows [0..3] / [4..7]

    float ah[4], aa[4], aj[4];
    #pragma unroll
    for (int r = 0; r < 4; r++) { ah[r] = 0.f; aa[r] = 0.f; aj[r] = 0.f; }

    #pragma unroll 4
    for (int k = 0; k < 128; k++) {
        float wn = Wn [ k       *128 + d];
        float wa = We1[ k       *128 + d];
        float wb = We1[(128 + k)*128 + d];
        #pragma unroll
        for (int r = 0; r < 4; r++) {
            float x = s_nf[(rg*4 + r)*128 + k];   // warp-uniform broadcast
            ah[r] = fmaf(x, wn, ah[r]);
            aa[r] = fmaf(x, wa, aa[r]);
            aj[r] = fmaf(x, wb, aj[r]);
        }
    }

    const float bnd = bn[d], bed = be1[d];
    #pragma unroll
    for (int r = 0; r < 4; r++) {
        int row = rg*4 + r;
        int gi  = (b*N_ + i0 + row)*D_ + d;
        g_h[gi]    = ah[r] + bnd;
        g_base[gi] = aa[r] + bed;
        s_t[d*9 + row] = aj[r];                   // conflict-free (stride 9)
    }
    __syncthreads();

    // write a_j transposed: [b][d][i0..i0+7]
    for (int idx = t; idx < 128*8; idx += 256) {
        int dd = idx >> 3, rr = idx & 7;
        g_ajT[(b*D_ + dd)*N_ + i0 + rr] = s_t[dd*9 + rr];
    }
}

// ---------------------------------------------------------------------------
// Kernel 2: fused edge-MLP scores -> masked softmax -> messages (w@h) ->
//           output GEMM + relu + residual -> layernorm.
// Block = (b, 8-row i-tile), 256 threads. Grid = 256 blocks.
// ---------------------------------------------------------------------------
__global__ void __launch_bounds__(256, 3) fused_kernel(
    const float* __restrict__ nf,
    const int*   __restrict__ adj,
    const float* __restrict__ rel,
    const float* __restrict__ We1,
    const float* __restrict__ We2,
    const float* __restrict__ Wa,
    const float* __restrict__ ba,
    const float* __restrict__ gamma,
    const float* __restrict__ beta,
    float* __restrict__ out)
{
    __shared__ float  s_sc[8*256];    // scores, then softmax weights w
    __shared__ float  s_bt[1024];     // baseT [d*8+i]; reused as x [i*128+d]
    __shared__ float  s_msg[8*128];   // messages
    __shared__ float4 s_w4[128];      // (w_relx, w_rely, w_dist, We2)[d]

    const int t  = threadIdx.x;
    const int b  = blockIdx.x >> 5;
    const int i0 = (blockIdx.x & 31) << 3;

    // ---- phase 0: stage base (transposed) and rel-weight columns ----
    for (int idx = t; idx < 1024; idx += 256) {
        int i = idx >> 7, d = idx & 127;
        s_bt[d*8 + i] = g_base[(b*N_ + i0 + i)*D_ + d];
    }
    if (t < 128)
        s_w4[t] = make_float4(We1[256*128 + t], We1[257*128 + t],
                              We1[258*128 + t], We2[t]);
    __syncthreads();

    // ---- phase 1: edge scores. lane <-> j (j = t), loop d outer, i inner.
    {
        const int j = t;
        float rx[8], ry[8], rd[8];
        unsigned mbits = 0u;
        #pragma unroll
        for (int i = 0; i < 8; i++) {
            float2 r = *(const float2*)(rel + (size_t)(((b*N_) + (i0 + i))*N_ + j)*2);
            rx[i] = r.x; ry[i] = r.y;
            rd[i] = sqrtf(r.x*r.x + r.y*r.y);
            if (adj[((b*N_) + (i0 + i))*N_ + j] != 0) mbits |= (1u << i);
        }
        float s[8];
        #pragma unroll
        for (int i = 0; i < 8; i++) s[i] = 0.f;

        const float* ajp = g_ajT + (size_t)b*D_*N_ + j;
        #pragma unroll 4
        for (int d = 0; d < 128; d++) {
            float  ajv = ajp[d*N_];            // coalesced 128B per warp
            float4 w4  = s_w4[d];              // broadcast
            const float4* bp = (const float4*)(s_bt + d*8);
            #pragma unroll
            for (int ig = 0; ig < 2; ig++) {
                float4 bs = bp[ig];            // broadcast LDS.128
                float v0 = fmaf(rx[ig*4+0], w4.x, fmaf(ry[ig*4+0], w4.y, fmaf(rd[ig*4+0], w4.z, bs.x + ajv)));
                float v1 = fmaf(rx[ig*4+1], w4.x, fmaf(ry[ig*4+1], w4.y, fmaf(rd[ig*4+1], w4.z, bs.y + ajv)));
                float v2 = fmaf(rx[ig*4+2], w4.x, fmaf(ry[ig*4+2], w4.y, fmaf(rd[ig*4+2], w4.z, bs.z + ajv)));
                float v3 = fmaf(rx[ig*4+3], w4.x, fmaf(ry[ig*4+3], w4.y, fmaf(rd[ig*4+3], w4.z, bs.w + ajv)));
                s[ig*4+0] = fmaf(fmaxf(v0, 0.f), w4.w, s[ig*4+0]);
                s[ig*4+1] = fmaf(fmaxf(v1, 0.f), w4.w, s[ig*4+1]);
                s[ig*4+2] = fmaf(fmaxf(v2, 0.f), w4.w, s[ig*4+2]);
                s[ig*4+3] = fmaf(fmaxf(v3, 0.f), w4.w, s[ig*4+3]);
            }
        }
        #pragma unroll
        for (int i = 0; i < 8; i++)
            s_sc[i*256 + j] = ((mbits >> i) & 1u) ? s[i] : -1e30f;
        // note: be2 omitted — softmax is shift-invariant.
    }
    __syncthreads();

    // ---- phase 2: masked softmax over j (warp w handles row w)
    {
        const int w = t >> 5, lane = t & 31;
        float v[8]; float m = -3.0e38f;
        #pragma unroll
        for (int k = 0; k < 8; k++) { v[k] = s_sc[w*256 + lane + 32*k]; m = fmaxf(m, v[k]); }
        #pragma unroll
        for (int o = 16; o > 0; o >>= 1) m = fmaxf(m, __shfl_xor_sync(0xffffffffu, m, o));
        float sum = 0.f;
        #pragma unroll
        for (int k = 0; k < 8; k++) { v[k] = __expf(v[k] - m); sum += v[k]; }
        #pragma unroll
        for (int o = 16; o > 0; o >>= 1) sum += __shfl_xor_sync(0xffffffffu, sum, o);
        float inv = 1.0f / sum;
        #pragma unroll
        for (int k = 0; k < 8; k++) s_sc[w*256 + lane + 32*k] = v[k] * inv;
    }
    __syncthreads();

    // ---- phase 3: messages[i][d] = sum_j w[i][j] * h[j][d]
    {
        const int d = t & 127, g = t >> 7;
        float m[4];
        #pragma unroll
        for (int r = 0; r < 4; r++) m[r] = 0.f;
        const float* hp = g_h + (size_t)b*N_*D_ + d;
        #pragma unroll 2
        for (int j = 0; j < 256; j += 4) {
            float hv0 = hp[(j+0)*D_];
            float hv1 = hp[(j+1)*D_];
            float hv2 = hp[(j+2)*D_];
            float hv3 = hp[(j+3)*D_];
            #pragma unroll
            for (int r = 0; r < 4; r++) {
                const float4 wq = *(const float4*)(s_sc + (g*4 + r)*256 + j);
                m[r] = fmaf(wq.w, hv3, fmaf(wq.z, hv2, fmaf(wq.y, hv1, fmaf(wq.x, hv0, m[r]))));
            }
        }
        #pragma unroll
        for (int r = 0; r < 4; r++) s_msg[(g*4 + r)*128 + d] = m[r];
    }
    __syncthreads();

    // ---- phase 4: aggregated = relu(msg @ Wa + ba); x = nf + aggregated
    {
        const int dq = t & 127, g = t >> 7;
        float a[4];
        #pragma unroll
        for (int r = 0; r < 4; r++) a[r] = 0.f;
        #pragma unroll 4
        for (int d = 0; d < 128; d++) {
            float wv = Wa[d*128 + dq];
            #pragma unroll
            for (int r = 0; r < 4; r++)
                a[r] = fmaf(s_msg[(g*4 + r)*128 + d], wv, a[r]);
        }
        const float bav = ba[dq];
        #pragma unroll
        for (int r = 0; r < 4; r++) {
            int i = g*4 + r;
            float x = nf[(b*N_ + i0 + i)*D_ + dq] + fmaxf(a[r] + bav, 0.f);
            s_bt[i*128 + dq] = x;    // baseT dead after phase 1; reuse as x
        }
    }
    __syncthreads();

    // ---- phase 5: layernorm over d, write output (warp w -> row w)
    {
        const int w = t >> 5, lane = t & 31;
        float4 xv = *(const float4*)(s_bt + w*128 + lane*4);
        float sm = xv.x + xv.y + xv.z + xv.w;
        float sq = fmaf(xv.x, xv.x, fmaf(xv.y, xv.y, fmaf(xv.z, xv.z, xv.w*xv.w)));
        #pragma unroll
        for (int o = 16; o > 0; o >>= 1) {
            sm += __shfl_xor_sync(0xffffffffu, sm, o);
            sq += __shfl_xor_sync(0xffffffffu, sq, o);
        }
        float mu   = sm * (1.0f/128.0f);
        float var  = fmaf(sq, 1.0f/128.0f, -mu*mu);
        float rstd = rsqrtf(var + 1e-5f);
        float4 gv = *(const float4*)(gamma + lane*4);
        float4 bv = *(const float4*)(beta  + lane*4);
        float4 o4;
        o4.x = fmaf((xv.x - mu)*rstd, gv.x, bv.x);
        o4.y = fmaf((xv.y - mu)*rstd, gv.y, bv.y);
        o4.z = fmaf((xv.z - mu)*rstd, gv.z, bv.z);
        o4.w = fmaf((xv.w - mu)*rstd, gv.w, bv.w);
        *(float4*)(out + (size_t)(b*N_ + i0 + w)*D_ + lane*4) = o4;
    }
}

extern "C" void kernel_launch(void* const* d_in, const int* in_sizes, int n_in,
                              void* d_out, int out_size)
{
    const float* nf    = (const float*)d_in[0];
    const int*   adj   = (const int*)  d_in[1];
    const float* rel   = (const float*)d_in[2];
    const float* Wn    = (const float*)d_in[3];
    const float* bn    = (const float*)d_in[4];
    const float* We1   = (const float*)d_in[5];
    const float* be1   = (const float*)d_in[6];
    const float* We2   = (const float*)d_in[7];
    // d_in[8] = be2: unused (softmax shift-invariance makes it a no-op)
    const float* Wa    = (const float*)d_in[9];
    const float* ba    = (const float*)d_in[10];
    const float* gamma = (const float*)d_in[11];
    const float* beta  = (const float*)d_in[12];
    float* out = (float*)d_out;

    precompute_kernel<<<256, 256>>>(nf, Wn, bn, We1, be1);
    fused_kernel<<<256, 256>>>(nf, adj, rel, We1, We2, Wa, ba, gamma, beta, out);
}

// round 3
// speedup vs baseline: 1.3140x; 1.0733x over previous
#include <cuda_runtime.h>
#include <math.h>

#define B_ 8
#define N_ 256
#define D_ 128

// Scratch (device globals — no allocation allowed in kernel_launch)
__device__ float g_h[B_*N_*D_];     // h = nf@Wn + bn            [b][i][d]
__device__ float g_base[B_*N_*D_];  // a_i + be1                 [b][i][d]
__device__ float g_ajT[B_*D_*N_];   // a_j d-pair major          [b][d/2][j][2]

// ---- packed f32x2 helpers ----
__device__ __forceinline__ unsigned long long pack2(float lo, float hi) {
    unsigned long long r;
    asm("mov.b64 %0,{%1,%2};" : "=l"(r) : "f"(lo), "f"(hi));
    return r;
}
__device__ __forceinline__ void unpack2(unsigned long long p, float& lo, float& hi) {
    asm("mov.b64 {%0,%1},%2;" : "=f"(lo), "=f"(hi) : "l"(p));
}
#define FMA2(d,a,b,c) asm("fma.rn.f32x2 %0,%1,%2,%3;" : "=l"(d) : "l"(a), "l"(b), "l"(c))
#define ADD2(d,a,b)   asm("add.rn.f32x2 %0,%1,%2;"    : "=l"(d) : "l"(a), "l"(b))

// ---------------------------------------------------------------------------
// Kernel 1: packed-f32x2 fused GEMVs, 8-row tiles, 256 blocks.
//   h    = nf @ Wn         + bn
//   base = nf @ We1[0:128] + be1
//   ajT  = nf @ We1[128:256]        (stored d-pair-major for kernel 2)
// Thread: dp = t&63 (d-pair), rg = t>>6 -> rows rg*2, rg*2+1.
// ---------------------------------------------------------------------------
__global__ void __launch_bounds__(256, 4) precompute_kernel(
    const float* __restrict__ nf,
    const float* __restrict__ Wn,  const float* __restrict__ bn,
    const float* __restrict__ We1, const float* __restrict__ be1)
{
    __shared__ float s_nf[8*128];
    const int t  = threadIdx.x;
    const int b  = blockIdx.x >> 5;
    const int i0 = (blockIdx.x & 31) << 3;

    const float* nfrow = nf + (b*N_ + i0)*D_;
    for (int idx = t; idx < 8*128; idx += 256)
        s_nf[idx] = nfrow[idx];
    __syncthreads();

    const int dp = t & 63;
    const int rg = t >> 6;          // 0..3 -> rows rg*2, rg*2+1
    const int r0 = rg*2, r1 = rg*2 + 1;

    unsigned long long hP0 = 0ull, hP1 = 0ull;
    unsigned long long aP0 = 0ull, aP1 = 0ull;
    unsigned long long jP0 = 0ull, jP1 = 0ull;

    #pragma unroll 4
    for (int k = 0; k < 128; k++) {
        unsigned long long wn = *(const unsigned long long*)&Wn [ k       *128 + 2*dp];
        unsigned long long wa = *(const unsigned long long*)&We1[ k       *128 + 2*dp];
        unsigned long long wb = *(const unsigned long long*)&We1[(128 + k)*128 + 2*dp];
        unsigned long long x0 = pack2(s_nf[r0*128 + k], s_nf[r0*128 + k]);
        unsigned long long x1 = pack2(s_nf[r1*128 + k], s_nf[r1*128 + k]);
        FMA2(hP0, x0, wn, hP0);  FMA2(hP1, x1, wn, hP1);
        FMA2(aP0, x0, wa, aP0);  FMA2(aP1, x1, wa, aP1);
        FMA2(jP0, x0, wb, jP0);  FMA2(jP1, x1, wb, jP1);
    }

    unsigned long long bnP = *(const unsigned long long*)&bn [2*dp];
    unsigned long long beP = *(const unsigned long long*)&be1[2*dp];
    ADD2(hP0, hP0, bnP);  ADD2(hP1, hP1, bnP);
    ADD2(aP0, aP0, beP);  ADD2(aP1, aP1, beP);

    unsigned long long* ghp = (unsigned long long*)g_h;
    unsigned long long* gbp = (unsigned long long*)g_base;
    unsigned long long* gjp = (unsigned long long*)g_ajT;
    ghp[(b*N_ + i0 + r0)*64 + dp] = hP0;
    ghp[(b*N_ + i0 + r1)*64 + dp] = hP1;
    gbp[(b*N_ + i0 + r0)*64 + dp] = aP0;
    gbp[(b*N_ + i0 + r1)*64 + dp] = aP1;
    gjp[(b*64 + dp)*256 + i0 + r0] = jP0;
    gjp[(b*64 + dp)*256 + i0 + r1] = jP1;
}

// ---------------------------------------------------------------------------
// Kernel 2: fused edge-MLP scores -> masked softmax -> messages (w@h) ->
//           output GEMM + relu + residual -> layernorm.
// Block = (b, 4-row i-tile), 256 threads. Grid = 512 blocks.
// Phase 1 fully packed f32x2 over d-pairs.
// ---------------------------------------------------------------------------
__global__ void __launch_bounds__(256, 4) fused_kernel(
    const float* __restrict__ nf,
    const int*   __restrict__ adj,
    const float* __restrict__ rel,
    const float* __restrict__ We1,
    const float* __restrict__ We2,
    const float* __restrict__ Wa,
    const float* __restrict__ ba,
    const float* __restrict__ gamma,
    const float* __restrict__ beta,
    float* __restrict__ out)
{
    __shared__ float      s_sc[4*256];   // scores -> softmax w; later reused as x
    __shared__ ulonglong2 s_w[128];      // per dp: {wxP,wyP},{wzP,weP}
    __shared__ ulonglong2 s_bt[128];     // per dp: {bsP_i0,bsP_i1},{bsP_i2,bsP_i3}
    __shared__ float      s_msg[4*128];  // messages

    const int t  = threadIdx.x;
    const int b  = blockIdx.x >> 6;
    const int i0 = (blockIdx.x & 63) << 2;

    // ---- phase 0: stage packed base tile + packed rel-weight columns ----
    {
        float* s_btf = (float*)s_bt;
        const float* gb = g_base + (b*N_ + i0)*D_;
        #pragma unroll
        for (int idx = t; idx < 512; idx += 256) {
            int i = idx >> 7, d = idx & 127;
            s_btf[(d >> 1)*8 + i*2 + (d & 1)] = gb[i*D_ + d];
        }
        float* s_wf = (float*)s_w;
        #pragma unroll
        for (int idx = t; idx < 512; idx += 256) {
            int dp = idx >> 3, c = idx & 7;
            int col = 2*dp + (c & 1), w = c >> 1;
            s_wf[idx] = (w < 3) ? We1[(256 + w)*128 + col] : We2[col];
        }
    }
    __syncthreads();

    // ---- phase 1: edge scores, packed over d-pairs. lane <-> j (j = t). ----
    {
        const int j = t;
        unsigned long long rxP[4], ryP[4], rdP[4];
        unsigned mbits = 0u;
        #pragma unroll
        for (int i = 0; i < 4; i++) {
            float2 r = *(const float2*)(rel + (size_t)(((b*N_) + (i0 + i))*N_ + j)*2);
            float rdv = sqrtf(r.x*r.x + r.y*r.y);
            rxP[i] = pack2(r.x, r.x);
            ryP[i] = pack2(r.y, r.y);
            rdP[i] = pack2(rdv, rdv);
            if (adj[((b*N_) + (i0 + i))*N_ + j] != 0) mbits |= (1u << i);
        }
        unsigned long long sP[4] = {0ull, 0ull, 0ull, 0ull};

        const unsigned long long* ajp =
            ((const unsigned long long*)g_ajT) + ((size_t)b*64*256 + j);

        #pragma unroll 2
        for (int dp = 0; dp < 64; dp++) {
            unsigned long long ajP = ajp[dp*256];   // LDG.64, coalesced over j
            ulonglong2 wA  = s_w [2*dp];            // {wxP, wyP}  (broadcast)
            ulonglong2 wB  = s_w [2*dp + 1];        // {wzP, weP}
            ulonglong2 b01 = s_bt[2*dp];            // {bsP_i0, bsP_i1}
            ulonglong2 b23 = s_bt[2*dp + 1];        // {bsP_i2, bsP_i3}

            #pragma unroll
            for (int i = 0; i < 4; i++) {
                unsigned long long bsP = (i == 0) ? b01.x : (i == 1) ? b01.y
                                       : (i == 2) ? b23.x : b23.y;
                unsigned long long v;
                ADD2(v, bsP, ajP);
                FMA2(v, rxP[i], wA.x, v);
                FMA2(v, ryP[i], wA.y, v);
                FMA2(v, rdP[i], wB.x, v);
                float lo, hi;
                unpack2(v, lo, hi);
                lo = fmaxf(lo, 0.f); hi = fmaxf(hi, 0.f);
                unsigned long long vr = pack2(lo, hi);
                FMA2(sP[i], vr, wB.y, sP[i]);
            }
        }

        #pragma unroll
        for (int i = 0; i < 4; i++) {
            float lo, hi;
            unpack2(sP[i], lo, hi);
            float s = lo + hi;
            s_sc[i*256 + j] = ((mbits >> i) & 1u) ? s : -1e30f;
        }
        // be2 omitted — softmax is shift-invariant.
    }
    __syncthreads();

    // ---- phase 2: masked softmax over j (warps 0-3, one row each) ----
    {
        const int w = t >> 5, lane = t & 31;
        if (w < 4) {
            float v[8]; float m = -3.0e38f;
            #pragma unroll
            for (int k = 0; k < 8; k++) { v[k] = s_sc[w*256 + lane + 32*k]; m = fmaxf(m, v[k]); }
            #pragma unroll
            for (int o = 16; o > 0; o >>= 1) m = fmaxf(m, __shfl_xor_sync(0xffffffffu, m, o));
            float sum = 0.f;
            #pragma unroll
            for (int k = 0; k < 8; k++) { v[k] = __expf(v[k] - m); sum += v[k]; }
            #pragma unroll
            for (int o = 16; o > 0; o >>= 1) sum += __shfl_xor_sync(0xffffffffu, sum, o);
            float inv = 1.0f / sum;
            #pragma unroll
            for (int k = 0; k < 8; k++) s_sc[w*256 + lane + 32*k] = v[k] * inv;
        }
    }
    __syncthreads();

    // ---- phase 3: messages[i][d] = sum_j w[i][j] * h[j][d] ----
    {
        const int d = t & 127, g = t >> 7;      // g in {0,1} -> rows g*2, g*2+1
        float m0 = 0.f, m1 = 0.f;
        const float* hp = g_h + (size_t)b*N_*D_ + d;
        const float* w0 = s_sc + (g*2    )*256;
        const float* w1 = s_sc + (g*2 + 1)*256;
        #pragma unroll 2
        for (int j = 0; j < 256; j += 4) {
            float hv0 = hp[(j+0)*D_];
            float hv1 = hp[(j+1)*D_];
            float hv2 = hp[(j+2)*D_];
            float hv3 = hp[(j+3)*D_];
            const float4 wa = *(const float4*)(w0 + j);
            const float4 wb = *(const float4*)(w1 + j);
            m0 = fmaf(wa.w, hv3, fmaf(wa.z, hv2, fmaf(wa.y, hv1, fmaf(wa.x, hv0, m0))));
            m1 = fmaf(wb.w, hv3, fmaf(wb.z, hv2, fmaf(wb.y, hv1, fmaf(wb.x, hv0, m1))));
        }
        s_msg[(g*2    )*128 + d] = m0;
        s_msg[(g*2 + 1)*128 + d] = m1;
    }
    __syncthreads();

    // ---- phase 4: aggregated = relu(msg @ Wa + ba); x = nf + aggregated ----
    {
        const int dq = t & 127, g = t >> 7;
        float a0 = 0.f, a1 = 0.f;
        const float* m0p = s_msg + (g*2    )*128;
        const float* m1p = s_msg + (g*2 + 1)*128;
        #pragma unroll 4
        for (int d = 0; d < 128; d++) {
            float wv = Wa[d*128 + dq];
            a0 = fmaf(m0p[d], wv, a0);
            a1 = fmaf(m1p[d], wv, a1);
        }
        const float bav = ba[dq];
        float* s_x = s_sc;   // scores dead after phase 3; reuse as x
        int r0 = g*2, r1 = g*2 + 1;
        s_x[r0*128 + dq] = nf[(b*N_ + i0 + r0)*D_ + dq] + fmaxf(a0 + bav, 0.f);
        s_x[r1*128 + dq] = nf[(b*N_ + i0 + r1)*D_ + dq] + fmaxf(a1 + bav, 0.f);
    }
    __syncthreads();

    // ---- phase 5: layernorm over d, write output (warps 0-3, one row each) ----
    {
        const int w = t >> 5, lane = t & 31;
        if (w < 4) {
            const float* s_x = s_sc;
            float4 xv = *(const float4*)(s_x + w*128 + lane*4);
            float sm = xv.x + xv.y + xv.z + xv.w;
            float sq = fmaf(xv.x, xv.x, fmaf(xv.y, xv.y, fmaf(xv.z, xv.z, xv.w*xv.w)));
            #pragma unroll
            for (int o = 16; o > 0; o >>= 1) {
                sm += __shfl_xor_sync(0xffffffffu, sm, o);
                sq += __shfl_xor_sync(0xffffffffu, sq, o);
            }
            float mu   = sm * (1.0f/128.0f);
            float var  = fmaf(sq, 1.0f/128.0f, -mu*mu);
            float rstd = rsqrtf(var + 1e-5f);
            float4 gv = *(const float4*)(gamma + lane*4);
            float4 bv = *(const float4*)(beta  + lane*4);
            float4 o4;
            o4.x = fmaf((xv.x - mu)*rstd, gv.x, bv.x);
            o4.y = fmaf((xv.y - mu)*rstd, gv.y, bv.y);
            o4.z = fmaf((xv.z - mu)*rstd, gv.z, bv.z);
            o4.w = fmaf((xv.w - mu)*rstd, gv.w, bv.w);
            *(float4*)(out + (size_t)(b*N_ + i0 + w)*D_ + lane*4) = o4;
        }
    }
}

extern "C" void kernel_launch(void* const* d_in, const int* in_sizes, int n_in,
                              void* d_out, int out_size)
{
    const float* nf    = (const float*)d_in[0];
    const int*   adj   = (const int*)  d_in[1];
    const float* rel   = (const float*)d_in[2];
    const float* Wn    = (const float*)d_in[3];
    const float* bn    = (const float*)d_in[4];
    const float* We1   = (const float*)d_in[5];
    const float* be1   = (const float*)d_in[6];
    const float* We2   = (const float*)d_in[7];
    // d_in[8] = be2: unused (softmax shift-invariance makes it a no-op)
    const float* Wa    = (const float*)d_in[9];
    const float* ba    = (const float*)d_in[10];
    const float* gamma = (const float*)d_in[11];
    const float* beta  = (const float*)d_in[12];
    float* out = (float*)d_out;

    precompute_kernel<<<256, 256>>>(nf, Wn, bn, We1, be1);
    fused_kernel<<<512, 256>>>(nf, adj, rel, We1, We2, Wa, ba, gamma, beta, out);
}

// round 4
// speedup vs baseline: 1.3750x; 1.0464x over previous
#include <cuda_runtime.h>
#include <math.h>

#define B_ 8
#define N_ 256
#define D_ 128

// Scratch (device globals — no allocation allowed in kernel_launch)
__device__ float g_h[B_*N_*D_];     // h = nf@Wn + bn            [b][i][d]
__device__ float g_base[B_*N_*D_];  // a_i + be1                 [b][i][d]
__device__ float g_ajT[B_*D_*N_];   // a_j d-pair major          [b][d/2][j][2]

// ---- packed f32x2 helpers ----
__device__ __forceinline__ unsigned long long pack2(float lo, float hi) {
    unsigned long long r;
    asm("mov.b64 %0,{%1,%2};" : "=l"(r) : "f"(lo), "f"(hi));
    return r;
}
__device__ __forceinline__ void unpack2(unsigned long long p, float& lo, float& hi) {
    asm("mov.b64 {%0,%1},%2;" : "=f"(lo), "=f"(hi) : "l"(p));
}
#define FMA2(d,a,b,c) asm("fma.rn.f32x2 %0,%1,%2,%3;" : "=l"(d) : "l"(a), "l"(b), "l"(c))
#define ADD2(d,a,b)   asm("add.rn.f32x2 %0,%1,%2;"    : "=l"(d) : "l"(a), "l"(b))

// ---------------------------------------------------------------------------
// Kernel 1: packed-f32x2 fused GEMVs, 8-row tiles, 256 blocks.
// ---------------------------------------------------------------------------
__global__ void __launch_bounds__(256, 4) precompute_kernel(
    const float* __restrict__ nf,
    const float* __restrict__ Wn,  const float* __restrict__ bn,
    const float* __restrict__ We1, const float* __restrict__ be1)
{
    __shared__ float s_nf[8*128];
    const int t  = threadIdx.x;
    const int b  = blockIdx.x >> 5;
    const int i0 = (blockIdx.x & 31) << 3;

    const float* nfrow = nf + (b*N_ + i0)*D_;
    for (int idx = t; idx < 8*128; idx += 256)
        s_nf[idx] = nfrow[idx];
    __syncthreads();

    const int dp = t & 63;
    const int rg = t >> 6;          // 0..3 -> rows rg*2, rg*2+1
    const int r0 = rg*2, r1 = rg*2 + 1;

    unsigned long long hP0 = 0ull, hP1 = 0ull;
    unsigned long long aP0 = 0ull, aP1 = 0ull;
    unsigned long long jP0 = 0ull, jP1 = 0ull;

    #pragma unroll 4
    for (int k = 0; k < 128; k++) {
        unsigned long long wn = *(const unsigned long long*)&Wn [ k       *128 + 2*dp];
        unsigned long long wa = *(const unsigned long long*)&We1[ k       *128 + 2*dp];
        unsigned long long wb = *(const unsigned long long*)&We1[(128 + k)*128 + 2*dp];
        unsigned long long x0 = pack2(s_nf[r0*128 + k], s_nf[r0*128 + k]);
        unsigned long long x1 = pack2(s_nf[r1*128 + k], s_nf[r1*128 + k]);
        FMA2(hP0, x0, wn, hP0);  FMA2(hP1, x1, wn, hP1);
        FMA2(aP0, x0, wa, aP0);  FMA2(aP1, x1, wa, aP1);
        FMA2(jP0, x0, wb, jP0);  FMA2(jP1, x1, wb, jP1);
    }

    unsigned long long bnP = *(const unsigned long long*)&bn [2*dp];
    unsigned long long beP = *(const unsigned long long*)&be1[2*dp];
    ADD2(hP0, hP0, bnP);  ADD2(hP1, hP1, bnP);
    ADD2(aP0, aP0, beP);  ADD2(aP1, aP1, beP);

    unsigned long long* ghp = (unsigned long long*)g_h;
    unsigned long long* gbp = (unsigned long long*)g_base;
    unsigned long long* gjp = (unsigned long long*)g_ajT;
    ghp[(b*N_ + i0 + r0)*64 + dp] = hP0;
    ghp[(b*N_ + i0 + r1)*64 + dp] = hP1;
    gbp[(b*N_ + i0 + r0)*64 + dp] = aP0;
    gbp[(b*N_ + i0 + r1)*64 + dp] = aP1;
    gjp[(b*64 + dp)*256 + i0 + r0] = jP0;
    gjp[(b*64 + dp)*256 + i0 + r1] = jP1;
}

// ---------------------------------------------------------------------------
// Kernel 2: fused edge-MLP -> softmax -> messages -> out GEMM -> layernorm.
// Block = (b, 4-row i-tile), 256 threads. Grid = 512 blocks.
// All global streams batched 8-deep for MLP (latency coverage).
// ---------------------------------------------------------------------------
__global__ void __launch_bounds__(256, 4) fused_kernel(
    const float* __restrict__ nf,
    const int*   __restrict__ adj,
    const float* __restrict__ rel,
    const float* __restrict__ We1,
    const float* __restrict__ We2,
    const float* __restrict__ Wa,
    const float* __restrict__ ba,
    const float* __restrict__ gamma,
    const float* __restrict__ beta,
    float* __restrict__ out)
{
    __shared__ float      s_sc[4*256];   // scores -> softmax w; later reused as x
    __shared__ ulonglong2 s_w[128];      // per dp: {wxP,wyP},{wzP,weP}
    __shared__ ulonglong2 s_bt[128];     // per dp: {bsP_i0,bsP_i1},{bsP_i2,bsP_i3}
    __shared__ float      s_msg[4*128];  // messages

    const int t  = threadIdx.x;
    const int b  = blockIdx.x >> 6;
    const int i0 = (blockIdx.x & 63) << 2;

    // ---- phase 0: stage packed base tile + packed rel-weight columns ----
    {
        float* s_btf = (float*)s_bt;
        const float* gb = g_base + (b*N_ + i0)*D_;
        #pragma unroll
        for (int idx = t; idx < 512; idx += 256) {
            int i = idx >> 7, d = idx & 127;
            s_btf[(d >> 1)*8 + i*2 + (d & 1)] = gb[i*D_ + d];
        }
        float* s_wf = (float*)s_w;
        #pragma unroll
        for (int idx = t; idx < 512; idx += 256) {
            int dp = idx >> 3, c = idx & 7;
            int col = 2*dp + (c & 1), w = c >> 1;
            s_wf[idx] = (w < 3) ? We1[(256 + w)*128 + col] : We2[col];
        }
    }
    __syncthreads();

    // ---- phase 1: edge scores, packed over d-pairs, 8-deep LDG batching ----
    {
        const int j = t;
        unsigned long long rxP[4], ryP[4], rdP[4];
        unsigned mbits = 0u;
        #pragma unroll
        for (int i = 0; i < 4; i++) {
            float2 r = *(const float2*)(rel + (size_t)(((b*N_) + (i0 + i))*N_ + j)*2);
            float rdv = sqrtf(r.x*r.x + r.y*r.y);
            rxP[i] = pack2(r.x, r.x);
            ryP[i] = pack2(r.y, r.y);
            rdP[i] = pack2(rdv, rdv);
            if (adj[((b*N_) + (i0 + i))*N_ + j] != 0) mbits |= (1u << i);
        }
        unsigned long long sP[4] = {0ull, 0ull, 0ull, 0ull};

        const unsigned long long* ajp =
            ((const unsigned long long*)g_ajT) + ((size_t)b*64*256 + j);

        #pragma unroll 1
        for (int dp0 = 0; dp0 < 64; dp0 += 8) {
            unsigned long long a8[8];
            #pragma unroll
            for (int u = 0; u < 8; u++) a8[u] = ajp[(dp0 + u)*256];   // 8 LDG.64 in flight

            #pragma unroll
            for (int u = 0; u < 8; u++) {
                const int dp = dp0 + u;
                ulonglong2 wA  = s_w [2*dp];            // {wxP, wyP}  (broadcast)
                ulonglong2 wB  = s_w [2*dp + 1];        // {wzP, weP}
                ulonglong2 b01 = s_bt[2*dp];            // {bsP_i0, bsP_i1}
                ulonglong2 b23 = s_bt[2*dp + 1];        // {bsP_i2, bsP_i3}

                #pragma unroll
                for (int i = 0; i < 4; i++) {
                    unsigned long long bsP = (i == 0) ? b01.x : (i == 1) ? b01.y
                                           : (i == 2) ? b23.x : b23.y;
                    unsigned long long v;
                    ADD2(v, bsP, a8[u]);
                    FMA2(v, rxP[i], wA.x, v);
                    FMA2(v, ryP[i], wA.y, v);
                    FMA2(v, rdP[i], wB.x, v);
                    float lo, hi;
                    unpack2(v, lo, hi);
                    lo = fmaxf(lo, 0.f); hi = fmaxf(hi, 0.f);
                    unsigned long long vr = pack2(lo, hi);
                    FMA2(sP[i], vr, wB.y, sP[i]);
                }
            }
        }

        #pragma unroll
        for (int i = 0; i < 4; i++) {
            float lo, hi;
            unpack2(sP[i], lo, hi);
            float s = lo + hi;
            s_sc[i*256 + j] = ((mbits >> i) & 1u) ? s : -1e30f;
        }
        // be2 omitted — softmax is shift-invariant.
    }
    __syncthreads();

    // ---- phase 2: masked softmax over j (warps 0-3, one row each) ----
    {
        const int w = t >> 5, lane = t & 31;
        if (w < 4) {
            float v[8]; float m = -3.0e38f;
            #pragma unroll
            for (int k = 0; k < 8; k++) { v[k] = s_sc[w*256 + lane + 32*k]; m = fmaxf(m, v[k]); }
            #pragma unroll
            for (int o = 16; o > 0; o >>= 1) m = fmaxf(m, __shfl_xor_sync(0xffffffffu, m, o));
            float sum = 0.f;
            #pragma unroll
            for (int k = 0; k < 8; k++) { v[k] = __expf(v[k] - m); sum += v[k]; }
            #pragma unroll
            for (int o = 16; o > 0; o >>= 1) sum += __shfl_xor_sync(0xffffffffu, sum, o);
            float inv = 1.0f / sum;
            #pragma unroll
            for (int k = 0; k < 8; k++) s_sc[w*256 + lane + 32*k] = v[k] * inv;
        }
    }
    __syncthreads();

    // ---- phase 3: messages[i][d] = sum_j w[i][j] * h[j][d], 8-deep LDG ----
    {
        const int d = t & 127, g = t >> 7;      // g in {0,1} -> rows g*2, g*2+1
        float m0 = 0.f, m1 = 0.f;
        const float* hp = g_h + (size_t)b*N_*D_ + d;
        const float* w0 = s_sc + (g*2    )*256;
        const float* w1 = s_sc + (g*2 + 1)*256;
        #pragma unroll 1
        for (int j0 = 0; j0 < 256; j0 += 8) {
            float hv[8];
            #pragma unroll
            for (int u = 0; u < 8; u++) hv[u] = hp[(j0 + u)*D_];    // 8 LDG.32 in flight
            const float4 wa0 = *(const float4*)(w0 + j0);
            const float4 wa1 = *(const float4*)(w0 + j0 + 4);
            const float4 wb0 = *(const float4*)(w1 + j0);
            const float4 wb1 = *(const float4*)(w1 + j0 + 4);
            m0 = fmaf(wa0.x, hv[0], m0); m1 = fmaf(wb0.x, hv[0], m1);
            m0 = fmaf(wa0.y, hv[1], m0); m1 = fmaf(wb0.y, hv[1], m1);
            m0 = fmaf(wa0.z, hv[2], m0); m1 = fmaf(wb0.z, hv[2], m1);
            m0 = fmaf(wa0.w, hv[3], m0); m1 = fmaf(wb0.w, hv[3], m1);
            m0 = fmaf(wa1.x, hv[4], m0); m1 = fmaf(wb1.x, hv[4], m1);
            m0 = fmaf(wa1.y, hv[5], m0); m1 = fmaf(wb1.y, hv[5], m1);
            m0 = fmaf(wa1.z, hv[6], m0); m1 = fmaf(wb1.z, hv[6], m1);
            m0 = fmaf(wa1.w, hv[7], m0); m1 = fmaf(wb1.w, hv[7], m1);
        }
        s_msg[(g*2    )*128 + d] = m0;
        s_msg[(g*2 + 1)*128 + d] = m1;
    }
    __syncthreads();

    // ---- phase 4: aggregated = relu(msg @ Wa + ba); x = nf + agg, 8-deep ----
    {
        const int dq = t & 127, g = t >> 7;
        float a0 = 0.f, a1 = 0.f;
        const float* m0p = s_msg + (g*2    )*128;
        const float* m1p = s_msg + (g*2 + 1)*128;
        #pragma unroll 1
        for (int d0 = 0; d0 < 128; d0 += 8) {
            float wv[8];
            #pragma unroll
            for (int u = 0; u < 8; u++) wv[u] = Wa[(d0 + u)*128 + dq];  // 8 LDG.32 in flight
            #pragma unroll
            for (int u = 0; u < 8; u++) {
                a0 = fmaf(m0p[d0 + u], wv[u], a0);
                a1 = fmaf(m1p[d0 + u], wv[u], a1);
            }
        }
        const float bav = ba[dq];
        float* s_x = s_sc;   // scores dead after phase 3; reuse as x
        int r0 = g*2, r1 = g*2 + 1;
        s_x[r0*128 + dq] = nf[(b*N_ + i0 + r0)*D_ + dq] + fmaxf(a0 + bav, 0.f);
        s_x[r1*128 + dq] = nf[(b*N_ + i0 + r1)*D_ + dq] + fmaxf(a1 + bav, 0.f);
    }
    __syncthreads();

    // ---- phase 5: layernorm over d, write output (warps 0-3, one row each) ----
    {
        const int w = t >> 5, lane = t & 31;
        if (w < 4) {
            const float* s_x = s_sc;
            float4 xv = *(const float4*)(s_x + w*128 + lane*4);
            float sm = xv.x + xv.y + xv.z + xv.w;
            float sq = fmaf(xv.x, xv.x, fmaf(xv.y, xv.y, fmaf(xv.z, xv.z, xv.w*xv.w)));
            #pragma unroll
            for (int o = 16; o > 0; o >>= 1) {
                sm += __shfl_xor_sync(0xffffffffu, sm, o);
                sq += __shfl_xor_sync(0xffffffffu, sq, o);
            }
            float mu   = sm * (1.0f/128.0f);
            float var  = fmaf(sq, 1.0f/128.0f, -mu*mu);
            float rstd = rsqrtf(var + 1e-5f);
            float4 gv = *(const float4*)(gamma + lane*4);
            float4 bv = *(const float4*)(beta  + lane*4);
            float4 o4;
            o4.x = fmaf((xv.x - mu)*rstd, gv.x, bv.x);
            o4.y = fmaf((xv.y - mu)*rstd, gv.y, bv.y);
            o4.z = fmaf((xv.z - mu)*rstd, gv.z, bv.z);
            o4.w = fmaf((xv.w - mu)*rstd, gv.w, bv.w);
            *(float4*)(out + (size_t)(b*N_ + i0 + w)*D_ + lane*4) = o4;
        }
    }
}

extern "C" void kernel_launch(void* const* d_in, const int* in_sizes, int n_in,
                              void* d_out, int out_size)
{
    const float* nf    = (const float*)d_in[0];
    const int*   adj   = (const int*)  d_in[1];
    const float* rel   = (const float*)d_in[2];
    const float* Wn    = (const float*)d_in[3];
    const float* bn    = (const float*)d_in[4];
    const float* We1   = (const float*)d_in[5];
    const float* be1   = (const float*)d_in[6];
    const float* We2   = (const float*)d_in[7];
    // d_in[8] = be2: unused (softmax shift-invariance makes it a no-op)
    const float* Wa    = (const float*)d_in[9];
    const float* ba    = (const float*)d_in[10];
    const float* gamma = (const float*)d_in[11];
    const float* beta  = (const float*)d_in[12];
    float* out = (float*)d_out;

    precompute_kernel<<<256, 256>>>(nf, Wn, bn, We1, be1);
    fused_kernel<<<512, 256>>>(nf, adj, rel, We1, We2, Wa, ba, gamma, beta, out);
}